// round 1
// baseline (speedup 1.0000x reference)
#include <cuda_runtime.h>
#include <cstdint>

// Problem constants
#define BSZ 64
#define SL 512
#define EM 1024
#define NH 16
#define HDIM 64
#define QK_SCALE 0.125f   // 1/sqrt(64)

// -------- scratch (device globals; no allocations) --------
__device__ float g_qin[BSZ * EM];          // kv_src row at mask_pos
__device__ float g_orig[BSZ * EM];         // model_output row at mask_pos
__device__ float g_q[BSZ * EM];            // scale*(q_in@Wq^T + bq)
__device__ float g_qk[BSZ * NH * EM];      // q_s @ Wk (per head)
__device__ float g_scores[BSZ * NH * SL];  // scores -> attn (in place)
__device__ float g_ctxw[BSZ * NH * EM];    // attn-weighted kv_src
__device__ float g_ctx[BSZ * EM];          // ctxw @ Wv^T + bv
__device__ float g_att[BSZ * EM];          // ctx @ Wout^T + bout

// ================= init accumulators with (scaled) biases =================
__global__ void k_init(const float* __restrict__ ipb, const float* __restrict__ opb) {
    int i = blockIdx.x * 256 + threadIdx.x;  // 65536 total
    if (i < BSZ * EM) {
        int o = i & (EM - 1);
        g_q[i]   = QK_SCALE * ipb[o];
        g_ctx[i] = ipb[2 * EM + o];
        g_att[i] = opb[o];
    }
}

// ================= mask_pos, q_in, origin_q =================
__global__ void k_setup(const float* __restrict__ mo, const float* __restrict__ kno,
                        const int* __restrict__ ids,
                        const int* __restrict__ pmask_id, const int* __restrict__ pknow_id) {
    __shared__ int smin;
    int b = blockIdx.x, t = threadIdx.x;
    if (t == 0) smin = SL;
    __syncthreads();
    int mid = *pmask_id;
    for (int s = t; s < SL; s += 256)
        if (ids[b * SL + s] == mid) atomicMin(&smin, s);
    __syncthreads();
    int p = (smin < SL) ? smin : 0;   // argmax of all-False -> 0
    bool isk = (ids[b * SL + p] == *pknow_id);
    const float* mrow = mo + (size_t)(b * SL + p) * EM;
    const float* krow = kno + b * EM;
    for (int e = t; e < EM; e += 256) {
        float m = mrow[e];
        g_orig[b * EM + e] = m;
        g_qin[b * EM + e]  = isk ? krow[e] : m;
    }
}

// ================= generic TN GEMM: C[64 x 1024] += alpha * A[64x1024] @ W[1024x1024]^T
// mode 0: A=g_qin, C=g_q, alpha=QK_SCALE (Wq)   mode 1: A=g_ctx, C=g_att, alpha=1 (Wout)
// grid (16 o-tiles, 8 k-slices), 256 thr. k-split accumulates via atomicAdd.
__global__ __launch_bounds__(256) void k_gemm_tn(const float* __restrict__ W, int mode) {
    __shared__ float As[64][33];
    __shared__ float Ws[64][33];
    const float* A = mode ? g_ctx : g_qin;
    float* C       = mode ? g_att : g_q;
    float alpha    = mode ? 1.0f : QK_SCALE;
    int o0 = blockIdx.x * 64;
    int kb = blockIdx.y * 128;
    int t = threadIdx.x;
    int db = t & 15, bb = t >> 4;
    float acc[16];
#pragma unroll
    for (int i = 0; i < 16; i++) acc[i] = 0.f;
    int lr = t >> 2, lc = (t & 3) << 3;
    for (int kc = kb; kc < kb + 128; kc += 32) {
        float4 a0 = *(const float4*)(A + lr * EM + kc + lc);
        float4 a1 = *(const float4*)(A + lr * EM + kc + lc + 4);
        float4 w0 = *(const float4*)(W + (size_t)(o0 + lr) * EM + kc + lc);
        float4 w1 = *(const float4*)(W + (size_t)(o0 + lr) * EM + kc + lc + 4);
        As[lr][lc] = a0.x; As[lr][lc + 1] = a0.y; As[lr][lc + 2] = a0.z; As[lr][lc + 3] = a0.w;
        As[lr][lc + 4] = a1.x; As[lr][lc + 5] = a1.y; As[lr][lc + 6] = a1.z; As[lr][lc + 7] = a1.w;
        Ws[lr][lc] = w0.x; Ws[lr][lc + 1] = w0.y; Ws[lr][lc + 2] = w0.z; Ws[lr][lc + 3] = w0.w;
        Ws[lr][lc + 4] = w1.x; Ws[lr][lc + 5] = w1.y; Ws[lr][lc + 6] = w1.z; Ws[lr][lc + 7] = w1.w;
        __syncthreads();
#pragma unroll
        for (int k = 0; k < 32; k++) {
            float av[4], wv[4];
#pragma unroll
            for (int i = 0; i < 4; i++) { av[i] = As[bb + 16 * i][k]; wv[i] = Ws[db + 16 * i][k]; }
#pragma unroll
            for (int i = 0; i < 4; i++)
#pragma unroll
                for (int j = 0; j < 4; j++) acc[i * 4 + j] += av[i] * wv[j];
        }
        __syncthreads();
    }
#pragma unroll
    for (int i = 0; i < 4; i++)
#pragma unroll
        for (int j = 0; j < 4; j++)
            atomicAdd(&C[(bb + 16 * i) * EM + o0 + db + 16 * j], alpha * acc[i * 4 + j]);
}

// ================= ctx = ctxw @ Wv_h^T per head, k-split, atomicAdd into g_ctx =================
__global__ __launch_bounds__(256) void k_gemm_ctx(const float* __restrict__ ipw) {
    __shared__ float As[64][33];
    __shared__ float Ws[64][33];
    int h = blockIdx.x;
    int kb = blockIdx.y * 128;
    const float* A = g_ctxw + h * EM;                        // row stride NH*EM
    const float* W = ipw + (size_t)(2 * EM + h * HDIM) * EM; // rows d=0..63
    int t = threadIdx.x;
    int db = t & 15, bb = t >> 4;
    float acc[16];
#pragma unroll
    for (int i = 0; i < 16; i++) acc[i] = 0.f;
    int lr = t >> 2, lc = (t & 3) << 3;
    for (int kc = kb; kc < kb + 128; kc += 32) {
        float4 a0 = *(const float4*)(A + (size_t)lr * (NH * EM) + kc + lc);
        float4 a1 = *(const float4*)(A + (size_t)lr * (NH * EM) + kc + lc + 4);
        float4 w0 = *(const float4*)(W + (size_t)lr * EM + kc + lc);
        float4 w1 = *(const float4*)(W + (size_t)lr * EM + kc + lc + 4);
        As[lr][lc] = a0.x; As[lr][lc + 1] = a0.y; As[lr][lc + 2] = a0.z; As[lr][lc + 3] = a0.w;
        As[lr][lc + 4] = a1.x; As[lr][lc + 5] = a1.y; As[lr][lc + 6] = a1.z; As[lr][lc + 7] = a1.w;
        Ws[lr][lc] = w0.x; Ws[lr][lc + 1] = w0.y; Ws[lr][lc + 2] = w0.z; Ws[lr][lc + 3] = w0.w;
        Ws[lr][lc + 4] = w1.x; Ws[lr][lc + 5] = w1.y; Ws[lr][lc + 6] = w1.z; Ws[lr][lc + 7] = w1.w;
        __syncthreads();
#pragma unroll
        for (int k = 0; k < 32; k++) {
            float av[4], wv[4];
#pragma unroll
            for (int i = 0; i < 4; i++) { av[i] = As[bb + 16 * i][k]; wv[i] = Ws[db + 16 * i][k]; }
#pragma unroll
            for (int i = 0; i < 4; i++)
#pragma unroll
                for (int j = 0; j < 4; j++) acc[i * 4 + j] += av[i] * wv[j];
        }
        __syncthreads();
    }
#pragma unroll
    for (int i = 0; i < 4; i++)
#pragma unroll
        for (int j = 0; j < 4; j++)
            atomicAdd(&g_ctx[(bb + 16 * i) * EM + h * HDIM + db + 16 * j], acc[i * 4 + j]);
}

// ================= qk[b,h,:] = q_s[b, h*64: ] @ Wk_h  (NN GEMM, K=64) =================
// grid (16 e-tiles, 16 heads)
__global__ __launch_bounds__(256) void k_qk(const float* __restrict__ ipw) {
    __shared__ float As[64][68];  // [b][k], pad keeps float4 alignment
    __shared__ float Bs[64][64];  // [k][e]
    int e0 = blockIdx.x * 64;
    int h  = blockIdx.y;
    int t = threadIdx.x;
    int lr = t >> 2, lc4 = (t & 3) << 4;
#pragma unroll
    for (int j = 0; j < 4; ++j) {
        float4 v = *(const float4*)(g_q + lr * EM + h * HDIM + lc4 + 4 * j);
        *(float4*)&As[lr][lc4 + 4 * j] = v;
        float4 w = *(const float4*)(ipw + (size_t)(EM + h * HDIM + lr) * EM + e0 + lc4 + 4 * j);
        *(float4*)&Bs[lr][lc4 + 4 * j] = w;
    }
    __syncthreads();
    int eb = t & 15, bb = t >> 4;
    float acc[16];
#pragma unroll
    for (int i = 0; i < 16; i++) acc[i] = 0.f;
#pragma unroll 8
    for (int k = 0; k < 64; k++) {
        float av[4], wv[4];
#pragma unroll
        for (int i = 0; i < 4; i++) { av[i] = As[bb + 16 * i][k]; wv[i] = Bs[k][eb + 16 * i]; }
#pragma unroll
        for (int i = 0; i < 4; i++)
#pragma unroll
            for (int j = 0; j < 4; j++) acc[i * 4 + j] += av[i] * wv[j];
    }
#pragma unroll
    for (int i = 0; i < 4; i++)
#pragma unroll
        for (int j = 0; j < 4; j++)
            g_qk[((bb + 16 * i) * NH + h) * EM + e0 + eb + 16 * j] = acc[i * 4 + j];
}

// ================= heavy pass 1: scores[b,h,s] = qk[b,h,:] . kv_src[b,s,:] =================
// grid (b=64, s-tile=2), 256 thr. kv_src materialized on the fly from ids/knowledge.
__global__ __launch_bounds__(256) void k_scores(const float* __restrict__ mo,
                                                const float* __restrict__ kno,
                                                const int* __restrict__ ids,
                                                const int* __restrict__ pknow_id) {
    __shared__ float kvs[256][33];  // [s][k], pad for conflict-free column reads
    __shared__ float qks[32][20];   // [k][h], pad 20 -> float4-aligned rows
    __shared__ int flag[256];
    int b = blockIdx.x;
    int s0 = blockIdx.y * 256;
    int t = threadIdx.x;
    int kid = *pknow_id;
    flag[t] = (ids[b * SL + s0 + t] == kid) ? 1 : 0;
    __syncthreads();

    int hg = t >> 7;      // 0..1 -> h block of 8
    int sp = t & 127;     // s in {sp, sp+128}
    float acc[16];
#pragma unroll
    for (int i = 0; i < 16; i++) acc[i] = 0.f;

    for (int k0 = 0; k0 < EM; k0 += 32) {
        // qk chunk: 16h x 32k, stored transposed [k][h]
        for (int i = t; i < 512; i += 256) {
            int h = i >> 5, kk = i & 31;
            qks[kk][h] = g_qk[(b * NH + h) * EM + k0 + kk];
        }
        // kv chunk: 256s x 32k
        int r0 = t >> 3, c = (t & 7) << 2;
#pragma unroll
        for (int j = 0; j < 8; ++j) {
            int r = r0 + (j << 5);
            const float* src = flag[r] ? (kno + b * EM)
                                       : (mo + (size_t)(b * SL + s0 + r) * EM);
            float4 v = *(const float4*)(src + k0 + c);
            kvs[r][c] = v.x; kvs[r][c + 1] = v.y; kvs[r][c + 2] = v.z; kvs[r][c + 3] = v.w;
        }
        __syncthreads();
#pragma unroll
        for (int kk = 0; kk < 32; ++kk) {
            float4 q0 = *(const float4*)&qks[kk][hg * 8];
            float4 q1 = *(const float4*)&qks[kk][hg * 8 + 4];
            float a = kvs[sp][kk];
            float bb2 = kvs[sp + 128][kk];
            acc[0] += q0.x * a;  acc[1] += q0.y * a;  acc[2] += q0.z * a;  acc[3] += q0.w * a;
            acc[4] += q1.x * a;  acc[5] += q1.y * a;  acc[6] += q1.z * a;  acc[7] += q1.w * a;
            acc[8]  += q0.x * bb2; acc[9]  += q0.y * bb2; acc[10] += q0.z * bb2; acc[11] += q0.w * bb2;
            acc[12] += q1.x * bb2; acc[13] += q1.y * bb2; acc[14] += q1.z * bb2; acc[15] += q1.w * bb2;
        }
        __syncthreads();
    }
#pragma unroll
    for (int j = 0; j < 8; ++j) {
        g_scores[(b * NH + hg * 8 + j) * SL + s0 + sp]       = acc[j];
        g_scores[(b * NH + hg * 8 + j) * SL + s0 + sp + 128] = acc[8 + j];
    }
}

// ================= softmax over s (512) per (b,h) row =================
__global__ void k_softmax() {
    int row = blockIdx.x;
    int t = threadIdx.x;
    float* p = g_scores + row * SL;
    float v[4];
#pragma unroll
    for (int i = 0; i < 4; i++) v[i] = p[t + 128 * i];
    float m = fmaxf(fmaxf(v[0], v[1]), fmaxf(v[2], v[3]));
#pragma unroll
    for (int o = 16; o; o >>= 1) m = fmaxf(m, __shfl_xor_sync(~0u, m, o));
    __shared__ float red[4];
    if ((t & 31) == 0) red[t >> 5] = m;
    __syncthreads();
    m = fmaxf(fmaxf(red[0], red[1]), fmaxf(red[2], red[3]));
    float s = 0.f;
#pragma unroll
    for (int i = 0; i < 4; i++) { v[i] = __expf(v[i] - m); s += v[i]; }
#pragma unroll
    for (int o = 16; o; o >>= 1) s += __shfl_xor_sync(~0u, s, o);
    __syncthreads();
    if ((t & 31) == 0) red[t >> 5] = s;
    __syncthreads();
    float inv = 1.f / (red[0] + red[1] + red[2] + red[3]);
#pragma unroll
    for (int i = 0; i < 4; i++) p[t + 128 * i] = v[i] * inv;
}

// ================= heavy pass 2: ctxw[b,h,e] = sum_s attn[b,h,s]*kv_src[b,s,e] =================
// grid (b=64, e-tile=4), 256 thr.
__global__ __launch_bounds__(256) void k_ctxw(const float* __restrict__ mo,
                                              const float* __restrict__ kno,
                                              const int* __restrict__ ids,
                                              const int* __restrict__ pknow_id) {
    __shared__ float kvs[32][256];  // [s][e] — e is fast index, conflict-free
    __shared__ float ps[32][20];    // [s][h]
    __shared__ int flag[SL];
    int b = blockIdx.x;
    int e0 = blockIdx.y * 256;
    int t = threadIdx.x;
    int kid = *pknow_id;
    for (int i = t; i < SL; i += 256) flag[i] = (ids[b * SL + i] == kid) ? 1 : 0;
    __syncthreads();

    int hg = t >> 7;
    int ep = t & 127;
    float acc[16];
#pragma unroll
    for (int i = 0; i < 16; i++) acc[i] = 0.f;

    for (int s0 = 0; s0 < SL; s0 += 32) {
        for (int i = t; i < 512; i += 256) {
            int h = i >> 5, ss = i & 31;
            ps[ss][h] = g_scores[(b * NH + h) * SL + s0 + ss];
        }
        int r = t >> 3;
#pragma unroll
        for (int j = 0; j < 8; ++j) {
            int c = (((t & 7) + (j << 3)) << 2);
            const float* src = flag[s0 + r] ? (kno + b * EM)
                                            : (mo + (size_t)(b * SL + s0 + r) * EM);
            float4 v = *(const float4*)(src + e0 + c);
            *(float4*)&kvs[r][c] = v;
        }
        __syncthreads();
#pragma unroll
        for (int ss = 0; ss < 32; ++ss) {
            float4 p0 = *(const float4*)&ps[ss][hg * 8];
            float4 p1 = *(const float4*)&ps[ss][hg * 8 + 4];
            float a = kvs[ss][ep];
            float bb2 = kvs[ss][ep + 128];
            acc[0] += p0.x * a;  acc[1] += p0.y * a;  acc[2] += p0.z * a;  acc[3] += p0.w * a;
            acc[4] += p1.x * a;  acc[5] += p1.y * a;  acc[6] += p1.z * a;  acc[7] += p1.w * a;
            acc[8]  += p0.x * bb2; acc[9]  += p0.y * bb2; acc[10] += p0.z * bb2; acc[11] += p0.w * bb2;
            acc[12] += p1.x * bb2; acc[13] += p1.y * bb2; acc[14] += p1.z * bb2; acc[15] += p1.w * bb2;
        }
        __syncthreads();
    }
#pragma unroll
    for (int j = 0; j < 8; ++j) {
        g_ctxw[(b * NH + hg * 8 + j) * EM + e0 + ep]       = acc[j];
        g_ctxw[(b * NH + hg * 8 + j) * EM + e0 + ep + 128] = acc[8 + j];
    }
}

// ================= final combine (+ robust bool-dtype detection) =================
__global__ void k_combine(const unsigned char* __restrict__ emk,
                          const float* __restrict__ strength,
                          float* __restrict__ out) {
    __shared__ int mode;  // 0=int32, 1=uint8, 2=float32
    int b = blockIdx.x, t = threadIdx.x;
    if (t == 0) {
        const unsigned* pw = (const unsigned*)emk;
        int isf = 0, isu = 0;
        for (int w = 0; w < 16; ++w) if (pw[w] == 0x3F800000u) isf = 1;
        if (!isf)
            for (int j = 0; j < 64; ++j) if ((j & 3) && emk[j]) isu = 1;
        mode = isf ? 2 : (isu ? 1 : 0);
    }
    __syncthreads();
    bool empty;
    if (mode == 1)      empty = emk[b] != 0;
    else if (mode == 2) empty = ((const unsigned*)emk)[b] != 0;
    else                empty = ((const int*)emk)[b] != 0;
    float st = *strength;
    for (int o = t; o < EM; o += 256) {
        float og = g_orig[b * EM + o];
        out[b * EM + o] = empty ? og : og + st * g_att[b * EM + o];
    }
}

extern "C" void kernel_launch(void* const* d_in, const int* in_sizes, int n_in,
                              void* d_out, int out_size) {
    const float* mo       = (const float*)d_in[0];   // model_output (64,512,1024)
    const float* kno      = (const float*)d_in[1];   // knowledge_output (64,1024)
    const float* ipw      = (const float*)d_in[2];   // in_proj_weight (3072,1024)
    const float* ipb      = (const float*)d_in[3];   // in_proj_bias (3072)
    const float* opw      = (const float*)d_in[4];   // out_proj_weight (1024,1024)
    const float* opb      = (const float*)d_in[5];   // out_proj_bias (1024)
    const float* strength = (const float*)d_in[6];   // attention_strength ()
    const int*   ids      = (const int*)d_in[7];     // input_ids (64,512)
    const unsigned char* emk = (const unsigned char*)d_in[8];  // empty_knowledge_mask (64) dtype-detected
    const int*   kid      = (const int*)d_in[9];     // knowledge_token_id
    const int*   midp     = (const int*)d_in[10];    // mask_token_id
    float* out = (float*)d_out;

    k_init<<<256, 256>>>(ipb, opb);
    k_setup<<<64, 256>>>(mo, kno, ids, midp, kid);
    k_gemm_tn<<<dim3(16, 8), 256>>>(ipw, 0);          // q = scale*(q_in@Wq^T + bq)
    k_qk<<<dim3(16, 16), 256>>>(ipw);                 // qk = q_s @ Wk per head
    k_scores<<<dim3(64, 2), 256>>>(mo, kno, ids, kid);
    k_softmax<<<BSZ * NH, 128>>>();
    k_ctxw<<<dim3(64, 4), 256>>>(mo, kno, ids, kid);
    k_gemm_ctx<<<dim3(16, 8), 256>>>(ipw);            // ctx = ctxw@Wv^T + bv
    k_gemm_tn<<<dim3(16, 8), 256>>>(opw, 1);          // att = ctx@Wout^T + bout
    k_combine<<<64, 256>>>(emk, strength, out);
}

// round 3
// speedup vs baseline: 1.3910x; 1.3910x over previous
#include <cuda_runtime.h>
#include <cstdint>

// Problem constants
#define BSZ 64
#define SL 512
#define EM 1024
#define NH 16
#define HDIM 64
#define QK_SCALE 0.125f   // 1/sqrt(64)

typedef unsigned long long ull;

__device__ __forceinline__ void ffma2(ull& d, ull a, ull b) {
    asm("fma.rn.f32x2 %0, %1, %2, %0;" : "+l"(d) : "l"(a), "l"(b));
}
__device__ __forceinline__ ull packf2(float x, float y) {
    ull r;
    asm("mov.b64 %0, {%1, %2};" : "=l"(r) : "f"(x), "f"(y));
    return r;
}
__device__ __forceinline__ float lo2(ull v) { return __uint_as_float((unsigned)v); }
__device__ __forceinline__ float hi2(ull v) { return __uint_as_float((unsigned)(v >> 32)); }

// -------- scratch (device globals; no allocations) --------
__device__ float g_qin[BSZ * EM];          // kv_src row at mask_pos
__device__ float g_orig[BSZ * EM];         // model_output row at mask_pos
__device__ float g_q[BSZ * EM];            // scale*(q_in@Wq^T + bq)
__device__ float g_qk[BSZ * NH * EM];      // q_s @ Wk (per head)
__device__ float g_scores[BSZ * NH * SL];  // scores -> attn (in place)
__device__ float g_ctxw[BSZ * NH * EM];    // attn-weighted kv_src
__device__ float g_ctx[BSZ * EM];          // ctxw @ Wv^T + bv
__device__ float g_att[BSZ * EM];          // ctx @ Wout^T + bout

// ================= init accumulators with (scaled) biases =================
__global__ void k_init(const float* __restrict__ ipb, const float* __restrict__ opb) {
    int i = blockIdx.x * 256 + threadIdx.x;  // 65536 total
    if (i < BSZ * EM) {
        int o = i & (EM - 1);
        g_q[i]   = QK_SCALE * ipb[o];
        g_ctx[i] = ipb[2 * EM + o];
        g_att[i] = opb[o];
    }
}

// ================= mask_pos, q_in, origin_q =================
__global__ void k_setup(const float* __restrict__ mo, const float* __restrict__ kno,
                        const int* __restrict__ ids,
                        const int* __restrict__ pmask_id, const int* __restrict__ pknow_id) {
    __shared__ int smin;
    int b = blockIdx.x, t = threadIdx.x;
    if (t == 0) smin = SL;
    __syncthreads();
    int mid = *pmask_id;
    for (int s = t; s < SL; s += 256)
        if (ids[b * SL + s] == mid) atomicMin(&smin, s);
    __syncthreads();
    int p = (smin < SL) ? smin : 0;   // argmax of all-False -> 0
    bool isk = (ids[b * SL + p] == *pknow_id);
    const float* mrow = mo + (size_t)(b * SL + p) * EM;
    const float* krow = kno + b * EM;
    for (int e = t; e < EM; e += 256) {
        float m = mrow[e];
        g_orig[b * EM + e] = m;
        g_qin[b * EM + e]  = isk ? krow[e] : m;
    }
}

// ================= generic TN GEMM: C[64 x 1024] += alpha * A[64x1024] @ W[1024x1024]^T
__global__ __launch_bounds__(256) void k_gemm_tn(const float* __restrict__ W, int mode) {
    __shared__ float As[64][33];
    __shared__ float Ws[64][33];
    const float* A = mode ? g_ctx : g_qin;
    float* C       = mode ? g_att : g_q;
    float alpha    = mode ? 1.0f : QK_SCALE;
    int o0 = blockIdx.x * 64;
    int kb = blockIdx.y * 128;
    int t = threadIdx.x;
    int db = t & 15, bb = t >> 4;
    float acc[16];
#pragma unroll
    for (int i = 0; i < 16; i++) acc[i] = 0.f;
    int lr = t >> 2, lc = (t & 3) << 3;
    for (int kc = kb; kc < kb + 128; kc += 32) {
        float4 a0 = *(const float4*)(A + lr * EM + kc + lc);
        float4 a1 = *(const float4*)(A + lr * EM + kc + lc + 4);
        float4 w0 = *(const float4*)(W + (size_t)(o0 + lr) * EM + kc + lc);
        float4 w1 = *(const float4*)(W + (size_t)(o0 + lr) * EM + kc + lc + 4);
        As[lr][lc] = a0.x; As[lr][lc + 1] = a0.y; As[lr][lc + 2] = a0.z; As[lr][lc + 3] = a0.w;
        As[lr][lc + 4] = a1.x; As[lr][lc + 5] = a1.y; As[lr][lc + 6] = a1.z; As[lr][lc + 7] = a1.w;
        Ws[lr][lc] = w0.x; Ws[lr][lc + 1] = w0.y; Ws[lr][lc + 2] = w0.z; Ws[lr][lc + 3] = w0.w;
        Ws[lr][lc + 4] = w1.x; Ws[lr][lc + 5] = w1.y; Ws[lr][lc + 6] = w1.z; Ws[lr][lc + 7] = w1.w;
        __syncthreads();
#pragma unroll
        for (int k = 0; k < 32; k++) {
            float av[4], wv[4];
#pragma unroll
            for (int i = 0; i < 4; i++) { av[i] = As[bb + 16 * i][k]; wv[i] = Ws[db + 16 * i][k]; }
#pragma unroll
            for (int i = 0; i < 4; i++)
#pragma unroll
                for (int j = 0; j < 4; j++) acc[i * 4 + j] += av[i] * wv[j];
        }
        __syncthreads();
    }
#pragma unroll
    for (int i = 0; i < 4; i++)
#pragma unroll
        for (int j = 0; j < 4; j++)
            atomicAdd(&C[(bb + 16 * i) * EM + o0 + db + 16 * j], alpha * acc[i * 4 + j]);
}

// ================= ctx = ctxw @ Wv_h^T per head, k-split, atomicAdd into g_ctx =================
__global__ __launch_bounds__(256) void k_gemm_ctx(const float* __restrict__ ipw) {
    __shared__ float As[64][33];
    __shared__ float Ws[64][33];
    int h = blockIdx.x;
    int kb = blockIdx.y * 128;
    const float* A = g_ctxw + h * EM;                        // row stride NH*EM
    const float* W = ipw + (size_t)(2 * EM + h * HDIM) * EM; // rows d=0..63
    int t = threadIdx.x;
    int db = t & 15, bb = t >> 4;
    float acc[16];
#pragma unroll
    for (int i = 0; i < 16; i++) acc[i] = 0.f;
    int lr = t >> 2, lc = (t & 3) << 3;
    for (int kc = kb; kc < kb + 128; kc += 32) {
        float4 a0 = *(const float4*)(A + (size_t)lr * (NH * EM) + kc + lc);
        float4 a1 = *(const float4*)(A + (size_t)lr * (NH * EM) + kc + lc + 4);
        float4 w0 = *(const float4*)(W + (size_t)lr * EM + kc + lc);
        float4 w1 = *(const float4*)(W + (size_t)lr * EM + kc + lc + 4);
        As[lr][lc] = a0.x; As[lr][lc + 1] = a0.y; As[lr][lc + 2] = a0.z; As[lr][lc + 3] = a0.w;
        As[lr][lc + 4] = a1.x; As[lr][lc + 5] = a1.y; As[lr][lc + 6] = a1.z; As[lr][lc + 7] = a1.w;
        Ws[lr][lc] = w0.x; Ws[lr][lc + 1] = w0.y; Ws[lr][lc + 2] = w0.z; Ws[lr][lc + 3] = w0.w;
        Ws[lr][lc + 4] = w1.x; Ws[lr][lc + 5] = w1.y; Ws[lr][lc + 6] = w1.z; Ws[lr][lc + 7] = w1.w;
        __syncthreads();
#pragma unroll
        for (int k = 0; k < 32; k++) {
            float av[4], wv[4];
#pragma unroll
            for (int i = 0; i < 4; i++) { av[i] = As[bb + 16 * i][k]; wv[i] = Ws[db + 16 * i][k]; }
#pragma unroll
            for (int i = 0; i < 4; i++)
#pragma unroll
                for (int j = 0; j < 4; j++) acc[i * 4 + j] += av[i] * wv[j];
        }
        __syncthreads();
    }
#pragma unroll
    for (int i = 0; i < 4; i++)
#pragma unroll
        for (int j = 0; j < 4; j++)
            atomicAdd(&g_ctx[(bb + 16 * i) * EM + h * HDIM + db + 16 * j], acc[i * 4 + j]);
}

// ================= qk[b,h,:] = q_s[b, h*64: ] @ Wk_h  (NN GEMM, K=64) =================
__global__ __launch_bounds__(256) void k_qk(const float* __restrict__ ipw) {
    __shared__ float As[64][68];
    __shared__ float Bs[64][64];
    int e0 = blockIdx.x * 64;
    int h  = blockIdx.y;
    int t = threadIdx.x;
    int lr = t >> 2, lc4 = (t & 3) << 4;
#pragma unroll
    for (int j = 0; j < 4; ++j) {
        float4 v = *(const float4*)(g_q + lr * EM + h * HDIM + lc4 + 4 * j);
        *(float4*)&As[lr][lc4 + 4 * j] = v;
        float4 w = *(const float4*)(ipw + (size_t)(EM + h * HDIM + lr) * EM + e0 + lc4 + 4 * j);
        *(float4*)&Bs[lr][lc4 + 4 * j] = w;
    }
    __syncthreads();
    int eb = t & 15, bb = t >> 4;
    float acc[16];
#pragma unroll
    for (int i = 0; i < 16; i++) acc[i] = 0.f;
#pragma unroll 8
    for (int k = 0; k < 64; k++) {
        float av[4], wv[4];
#pragma unroll
        for (int i = 0; i < 4; i++) { av[i] = As[bb + 16 * i][k]; wv[i] = Bs[k][eb + 16 * i]; }
#pragma unroll
        for (int i = 0; i < 4; i++)
#pragma unroll
            for (int j = 0; j < 4; j++) acc[i * 4 + j] += av[i] * wv[j];
    }
#pragma unroll
    for (int i = 0; i < 4; i++)
#pragma unroll
        for (int j = 0; j < 4; j++)
            g_qk[((bb + 16 * i) * NH + h) * EM + e0 + eb + 16 * j] = acc[i * 4 + j];
}

// ================= heavy pass 1 (f32x2, packed along k) =================
// scores[b,h,s] = qk[b,h,:] . kv_src[b,s,:].  grid (64, 4), 128 threads.
// Thread: hg=(t>>6)&1 -> 8 heads, sp=t&63 -> s in {sp, sp+64} of a 128-s chunk.
__global__ __launch_bounds__(128) void k_scores(const float* __restrict__ mo,
                                                const float* __restrict__ kno,
                                                const int* __restrict__ ids,
                                                const int* __restrict__ pknow_id) {
    __shared__ ull kvs2[128][33];  // [s][k2] packed (k,k+1); 33.8KB
    __shared__ ull qks2[32][18];   // [k2][h] packed (k,k+1); 4.6KB
    __shared__ int flag[128];
    int b = blockIdx.x;
    int s0 = blockIdx.y * 128;
    int t = threadIdx.x;
    int kid = *pknow_id;
    flag[t] = (ids[b * SL + s0 + t] == kid) ? 1 : 0;
    __syncthreads();

    int hg = (t >> 6) & 1;
    int sp = t & 63;
    ull acc[16];
#pragma unroll
    for (int i = 0; i < 16; i++) acc[i] = 0ull;

    for (int k0 = 0; k0 < EM; k0 += 64) {
        // qk tile: 16h x 32k2
        for (int i = t; i < 512; i += 128) {
            int h = i >> 5, k2 = i & 31;
            qks2[k2][h] = *(const ull*)(g_qk + (size_t)(b * NH + h) * EM + k0 + 2 * k2);
        }
        // kv tile: one row per thread, 64 floats
        {
            const float* src = flag[t] ? (kno + (size_t)b * EM)
                                       : (mo + (size_t)(b * SL + s0 + t) * EM);
#pragma unroll
            for (int j = 0; j < 16; j++) {
                float4 v = *(const float4*)(src + k0 + 4 * j);
                kvs2[t][2 * j]     = packf2(v.x, v.y);
                kvs2[t][2 * j + 1] = packf2(v.z, v.w);
            }
        }
        __syncthreads();
#pragma unroll 8
        for (int k2 = 0; k2 < 32; k2++) {
            ull ka = kvs2[sp][k2];
            ull kb = kvs2[sp + 64][k2];
            ulonglong2 q01 = *(const ulonglong2*)&qks2[k2][hg * 8];
            ulonglong2 q23 = *(const ulonglong2*)&qks2[k2][hg * 8 + 2];
            ulonglong2 q45 = *(const ulonglong2*)&qks2[k2][hg * 8 + 4];
            ulonglong2 q67 = *(const ulonglong2*)&qks2[k2][hg * 8 + 6];
            ffma2(acc[0],  q01.x, ka); ffma2(acc[1],  q01.x, kb);
            ffma2(acc[2],  q01.y, ka); ffma2(acc[3],  q01.y, kb);
            ffma2(acc[4],  q23.x, ka); ffma2(acc[5],  q23.x, kb);
            ffma2(acc[6],  q23.y, ka); ffma2(acc[7],  q23.y, kb);
            ffma2(acc[8],  q45.x, ka); ffma2(acc[9],  q45.x, kb);
            ffma2(acc[10], q45.y, ka); ffma2(acc[11], q45.y, kb);
            ffma2(acc[12], q67.x, ka); ffma2(acc[13], q67.x, kb);
            ffma2(acc[14], q67.y, ka); ffma2(acc[15], q67.y, kb);
        }
        __syncthreads();
    }
#pragma unroll
    for (int h = 0; h < 8; h++) {
        int row = (b * NH + hg * 8 + h) * SL + s0;
        g_scores[row + sp]      = lo2(acc[2 * h])     + hi2(acc[2 * h]);
        g_scores[row + sp + 64] = lo2(acc[2 * h + 1]) + hi2(acc[2 * h + 1]);
    }
}

// ================= softmax over s (512) per (b,h) row =================
__global__ void k_softmax() {
    int row = blockIdx.x;
    int t = threadIdx.x;
    float* p = g_scores + row * SL;
    float v[4];
#pragma unroll
    for (int i = 0; i < 4; i++) v[i] = p[t + 128 * i];
    float m = fmaxf(fmaxf(v[0], v[1]), fmaxf(v[2], v[3]));
#pragma unroll
    for (int o = 16; o; o >>= 1) m = fmaxf(m, __shfl_xor_sync(~0u, m, o));
    __shared__ float red[4];
    if ((t & 31) == 0) red[t >> 5] = m;
    __syncthreads();
    m = fmaxf(fmaxf(red[0], red[1]), fmaxf(red[2], red[3]));
    float s = 0.f;
#pragma unroll
    for (int i = 0; i < 4; i++) { v[i] = __expf(v[i] - m); s += v[i]; }
#pragma unroll
    for (int o = 16; o; o >>= 1) s += __shfl_xor_sync(~0u, s, o);
    __syncthreads();
    if ((t & 31) == 0) red[t >> 5] = s;
    __syncthreads();
    float inv = 1.f / (red[0] + red[1] + red[2] + red[3]);
#pragma unroll
    for (int i = 0; i < 4; i++) p[t + 128 * i] = v[i] * inv;
}

// ================= heavy pass 2 (f32x2, packed along e) =================
// ctxw[b,h,e] = sum_s attn[b,h,s]*kv_src[b,s,e].  grid (64, 2), 256 threads.
// Thread: hg=t>>7 -> 8 heads, ep=t&127 -> e2 slots {ep, ep+128} of a 512-e chunk.
__global__ __launch_bounds__(256) void k_ctxw(const float* __restrict__ mo,
                                              const float* __restrict__ kno,
                                              const int* __restrict__ ids,
                                              const int* __restrict__ pknow_id) {
    __shared__ ull kvt2[16][257];  // [s][e2] packed (e,e+1); 32.9KB
    __shared__ ull ps2[16][18];    // [s][h] attn duplicated in both lanes; 2.3KB
    __shared__ int flag[SL];
    int b = blockIdx.x;
    int e0 = blockIdx.y * 512;
    int t = threadIdx.x;
    int kid = *pknow_id;
    for (int i = t; i < SL; i += 256) flag[i] = (ids[b * SL + i] == kid) ? 1 : 0;
    __syncthreads();

    int hg = t >> 7;
    int ep = t & 127;
    ull acc[16];
#pragma unroll
    for (int i = 0; i < 16; i++) acc[i] = 0ull;

    for (int s0 = 0; s0 < SL; s0 += 16) {
        // attn tile, duplicated into both f32x2 lanes
        {
            int ss = t >> 4, h = t & 15;
            float v = g_scores[(b * NH + h) * SL + s0 + ss];
            unsigned u = __float_as_uint(v);
            ps2[ss][h] = (ull)u | ((ull)u << 32);
        }
        // kv tile: 16 rows x 512 floats; 16 threads per row
        {
            int r = t >> 4, c0 = (t & 15) * 4;
            const float* src = flag[s0 + r] ? (kno + (size_t)b * EM)
                                            : (mo + (size_t)(b * SL + s0 + r) * EM);
#pragma unroll
            for (int j = 0; j < 8; j++) {
                int c = c0 + 64 * j;
                float4 v = *(const float4*)(src + e0 + c);
                kvt2[r][c >> 1]       = packf2(v.x, v.y);
                kvt2[r][(c >> 1) + 1] = packf2(v.z, v.w);
            }
        }
        __syncthreads();
#pragma unroll 8
        for (int ss = 0; ss < 16; ss++) {
            ull ka = kvt2[ss][ep];
            ull kb = kvt2[ss][ep + 128];
            ulonglong2 p01 = *(const ulonglong2*)&ps2[ss][hg * 8];
            ulonglong2 p23 = *(const ulonglong2*)&ps2[ss][hg * 8 + 2];
            ulonglong2 p45 = *(const ulonglong2*)&ps2[ss][hg * 8 + 4];
            ulonglong2 p67 = *(const ulonglong2*)&ps2[ss][hg * 8 + 6];
            ffma2(acc[0],  p01.x, ka); ffma2(acc[1],  p01.x, kb);
            ffma2(acc[2],  p01.y, ka); ffma2(acc[3],  p01.y, kb);
            ffma2(acc[4],  p23.x, ka); ffma2(acc[5],  p23.x, kb);
            ffma2(acc[6],  p23.y, ka); ffma2(acc[7],  p23.y, kb);
            ffma2(acc[8],  p45.x, ka); ffma2(acc[9],  p45.x, kb);
            ffma2(acc[10], p45.y, ka); ffma2(acc[11], p45.y, kb);
            ffma2(acc[12], p67.x, ka); ffma2(acc[13], p67.x, kb);
            ffma2(acc[14], p67.y, ka); ffma2(acc[15], p67.y, kb);
        }
        __syncthreads();
    }
#pragma unroll
    for (int h = 0; h < 8; h++) {
        size_t g = (size_t)(b * NH + hg * 8 + h) * EM + e0;
        *(ull*)&g_ctxw[g + 2 * ep]         = acc[2 * h];
        *(ull*)&g_ctxw[g + 2 * (ep + 128)] = acc[2 * h + 1];
    }
}

// ================= final combine (+ robust bool-dtype detection) =================
__global__ void k_combine(const unsigned char* __restrict__ emk,
                          const float* __restrict__ strength,
                          float* __restrict__ out) {
    __shared__ int mode;  // 0=int32, 1=uint8, 2=float32
    int b = blockIdx.x, t = threadIdx.x;
    if (t == 0) {
        const unsigned* pw = (const unsigned*)emk;
        int isf = 0, isu = 0;
        for (int w = 0; w < 16; ++w) if (pw[w] == 0x3F800000u) isf = 1;
        if (!isf)
            for (int j = 0; j < 64; ++j) if ((j & 3) && emk[j]) isu = 1;
        mode = isf ? 2 : (isu ? 1 : 0);
    }
    __syncthreads();
    bool empty;
    if (mode == 1)      empty = emk[b] != 0;
    else if (mode == 2) empty = ((const unsigned*)emk)[b] != 0;
    else                empty = ((const int*)emk)[b] != 0;
    float st = *strength;
    for (int o = t; o < EM; o += 256) {
        float og = g_orig[b * EM + o];
        out[b * EM + o] = empty ? og : og + st * g_att[b * EM + o];
    }
}

extern "C" void kernel_launch(void* const* d_in, const int* in_sizes, int n_in,
                              void* d_out, int out_size) {
    const float* mo       = (const float*)d_in[0];
    const float* kno      = (const float*)d_in[1];
    const float* ipw      = (const float*)d_in[2];
    const float* ipb      = (const float*)d_in[3];
    const float* opw      = (const float*)d_in[4];
    const float* opb      = (const float*)d_in[5];
    const float* strength = (const float*)d_in[6];
    const int*   ids      = (const int*)d_in[7];
    const unsigned char* emk = (const unsigned char*)d_in[8];
    const int*   kid      = (const int*)d_in[9];
    const int*   midp     = (const int*)d_in[10];
    float* out = (float*)d_out;

    k_init<<<256, 256>>>(ipb, opb);
    k_setup<<<64, 256>>>(mo, kno, ids, midp, kid);
    k_gemm_tn<<<dim3(16, 8), 256>>>(ipw, 0);          // q = scale*(q_in@Wq^T + bq)
    k_qk<<<dim3(16, 16), 256>>>(ipw);                 // qk = q_s @ Wk per head
    k_scores<<<dim3(64, 4), 128>>>(mo, kno, ids, kid);
    k_softmax<<<BSZ * NH, 128>>>();
    k_ctxw<<<dim3(64, 2), 256>>>(mo, kno, ids, kid);
    k_gemm_ctx<<<dim3(16, 8), 256>>>(ipw);            // ctx = ctxw@Wv^T + bv
    k_gemm_tn<<<dim3(16, 8), 256>>>(opw, 1);          // att = ctx@Wout^T + bout
    k_combine<<<64, 256>>>(emk, strength, out);
}